// round 1
// baseline (speedup 1.0000x reference)
#include <cuda_runtime.h>
#include <math.h>

#define N_NODES 100000
#define N_EDGES 800000
#define DIM 128

// ---------------- scratch (no cudaMalloc allowed) ----------------
__device__ float  g_xw[N_NODES * DIM];   // GEMM output / aggregation input
__device__ float  g_h [N_NODES * DIM];   // hidden layer output
__device__ int    g_deg_out[N_NODES];
__device__ int    g_deg_in [N_NODES];
__device__ float  g_sout[N_NODES];       // deg_out^-1/2
__device__ float  g_sin [N_NODES];       // deg_in^-1/2
__device__ int    g_rowptr[N_NODES + 1];
__device__ int    g_cursor[N_NODES];
__device__ int    g_cols[N_EDGES];       // CSR column (src) indices grouped by dst
__device__ double g_sum [DIM];
__device__ double g_sumsq[DIM];
__device__ float  g_mean[DIM];
__device__ float  g_istd[DIM];

// ---------------- small utility kernels ----------------
__global__ void zero_deg_kernel() {
    int i = blockIdx.x * blockDim.x + threadIdx.x;
    if (i < N_NODES) { g_deg_out[i] = 0; g_deg_in[i] = 0; }
}

__global__ void zero_stats_kernel() {
    int i = threadIdx.x;
    if (i < DIM) { g_sum[i] = 0.0; g_sumsq[i] = 0.0; }
}

__global__ void degree_kernel(const int* __restrict__ src, const int* __restrict__ dst) {
    int i = blockIdx.x * blockDim.x + threadIdx.x;
    if (i < N_EDGES) {
        atomicAdd(&g_deg_out[src[i]], 1);
        atomicAdd(&g_deg_in [dst[i]], 1);
    }
}

__global__ void scale_kernel() {
    int i = blockIdx.x * blockDim.x + threadIdx.x;
    if (i < N_NODES) {
        int dout = g_deg_out[i]; if (dout < 1) dout = 1;
        int din  = g_deg_in [i]; if (din  < 1) din  = 1;
        g_sout[i] = rsqrtf((float)dout);
        g_sin [i] = rsqrtf((float)din);
    }
}

// single-block exclusive scan of g_deg_in -> g_rowptr (and init cursors)
__global__ void scan_kernel() {
    __shared__ int warp_sums[32];
    __shared__ int s_carry;
    int tid = threadIdx.x, lane = tid & 31, wid = tid >> 5;
    if (tid == 0) s_carry = 0;
    __syncthreads();
    for (int base = 0; base < N_NODES; base += 1024) {
        int i = base + tid;
        int v = (i < N_NODES) ? g_deg_in[i] : 0;
        int x = v;
        #pragma unroll
        for (int off = 1; off < 32; off <<= 1) {
            int t = __shfl_up_sync(0xffffffffu, x, off);
            if (lane >= off) x += t;
        }
        if (lane == 31) warp_sums[wid] = x;
        __syncthreads();
        if (wid == 0) {
            int ws = warp_sums[lane];
            #pragma unroll
            for (int off = 1; off < 32; off <<= 1) {
                int t = __shfl_up_sync(0xffffffffu, ws, off);
                if (lane >= off) ws += t;
            }
            warp_sums[lane] = ws;
        }
        __syncthreads();
        int warp_off = (wid > 0) ? warp_sums[wid - 1] : 0;
        int incl = x + warp_off;
        int carry = s_carry;
        int excl = incl - v + carry;
        if (i < N_NODES) { g_rowptr[i] = excl; g_cursor[i] = excl; }
        __syncthreads();
        if (tid == 1023) s_carry = carry + incl;
        __syncthreads();
    }
    if (threadIdx.x == 0) g_rowptr[N_NODES] = s_carry;
}

__global__ void scatter_kernel(const int* __restrict__ src, const int* __restrict__ dst) {
    int i = blockIdx.x * blockDim.x + threadIdx.x;
    if (i < N_EDGES) {
        int p = atomicAdd(&g_cursor[dst[i]], 1);
        g_cols[p] = src[i];
    }
}

// ---------------- GEMM: Y = (diag(g_sout) * X) @ W ----------------
// W fully staged in smem (64KB). Tile: 32 rows x 128 cols, 256 threads,
// thread (r = tid/8, c = (tid%8)*16) computes 16 outputs.
#define GEMM_BLOCKS 304
#define GEMM_SMEM ((DIM * DIM + 32 * 132) * (int)sizeof(float))

__global__ void __launch_bounds__(256) gemm_scale_kernel(
    const float* __restrict__ X, const float* __restrict__ W,
    float* __restrict__ Y)
{
    extern __shared__ float smem[];
    float* Ws = smem;                 // [128][128]
    float* Xs = smem + DIM * DIM;     // [32][132] (padded)

    // stage W
    for (int i = threadIdx.x * 4; i < DIM * DIM; i += 256 * 4) {
        *(float4*)&Ws[i] = *(const float4*)&W[i];
    }

    int r = threadIdx.x >> 3;
    int c = (threadIdx.x & 7) * 16;
    int ntiles = (N_NODES + 31) / 32;

    for (int tile = blockIdx.x; tile < ntiles; tile += gridDim.x) {
        int row0 = tile * 32;
        __syncthreads();
        // stage 32 rows of X, scaled
        for (int idx = threadIdx.x * 4; idx < 32 * DIM; idx += 1024) {
            int rr = idx >> 7, kk = idx & 127;
            int grow = row0 + rr;
            float4 xv = make_float4(0.f, 0.f, 0.f, 0.f);
            if (grow < N_NODES) {
                xv = *(const float4*)&X[grow * DIM + kk];
                float s = g_sout[grow];
                xv.x *= s; xv.y *= s; xv.z *= s; xv.w *= s;
            }
            *(float4*)&Xs[rr * 132 + kk] = xv;
        }
        __syncthreads();

        float acc[16];
        #pragma unroll
        for (int j = 0; j < 16; j++) acc[j] = 0.f;

        #pragma unroll 4
        for (int k = 0; k < DIM; k++) {
            float xv = Xs[r * 132 + k];
            const float4* wr = (const float4*)&Ws[k * DIM + c];
            float4 w0 = wr[0], w1 = wr[1], w2 = wr[2], w3 = wr[3];
            acc[0]  += xv * w0.x; acc[1]  += xv * w0.y; acc[2]  += xv * w0.z; acc[3]  += xv * w0.w;
            acc[4]  += xv * w1.x; acc[5]  += xv * w1.y; acc[6]  += xv * w1.z; acc[7]  += xv * w1.w;
            acc[8]  += xv * w2.x; acc[9]  += xv * w2.y; acc[10] += xv * w2.z; acc[11] += xv * w2.w;
            acc[12] += xv * w3.x; acc[13] += xv * w3.y; acc[14] += xv * w3.z; acc[15] += xv * w3.w;
        }

        int grow = row0 + r;
        if (grow < N_NODES) {
            float4* yp = (float4*)&Y[grow * DIM + c];
            yp[0] = make_float4(acc[0],  acc[1],  acc[2],  acc[3]);
            yp[1] = make_float4(acc[4],  acc[5],  acc[6],  acc[7]);
            yp[2] = make_float4(acc[8],  acc[9],  acc[10], acc[11]);
            yp[3] = make_float4(acc[12], acc[13], acc[14], acc[15]);
        }
    }
}

// ---------------- CSR aggregation: out[v] = f(sum_{e in in(v)} Xw[src_e]) ----------------
// one warp per dst node; each lane owns 4 columns (float4)
__global__ void agg_kernel(const float* __restrict__ Xw, const float* __restrict__ bias,
                           float* __restrict__ out, int do_relu)
{
    int warp = (blockIdx.x * blockDim.x + threadIdx.x) >> 5;
    int lane = threadIdx.x & 31;
    if (warp >= N_NODES) return;
    int r0 = g_rowptr[warp];
    int r1 = g_rowptr[warp + 1];
    float4 acc = make_float4(0.f, 0.f, 0.f, 0.f);
    for (int e = r0; e < r1; e++) {
        int csrc = g_cols[e];
        float4 v = *(const float4*)&Xw[csrc * DIM + lane * 4];
        acc.x += v.x; acc.y += v.y; acc.z += v.z; acc.w += v.w;
    }
    float s = g_sin[warp];
    float4 b = *(const float4*)&bias[lane * 4];
    float4 o;
    o.x = acc.x * s + b.x; o.y = acc.y * s + b.y;
    o.z = acc.z * s + b.z; o.w = acc.w * s + b.w;
    if (do_relu) {
        o.x = fmaxf(o.x, 0.f); o.y = fmaxf(o.y, 0.f);
        o.z = fmaxf(o.z, 0.f); o.w = fmaxf(o.w, 0.f);
    }
    *(float4*)&out[warp * DIM + lane * 4] = o;
}

// ---------------- column stats + z-score ----------------
__global__ void stats_kernel(const float* __restrict__ h) {
    int col = threadIdx.x;  // blockDim = 128
    float sum = 0.f, sq = 0.f;
    for (int row = blockIdx.x; row < N_NODES; row += gridDim.x) {
        float v = h[row * DIM + col];
        sum += v; sq += v * v;
    }
    atomicAdd(&g_sum[col], (double)sum);
    atomicAdd(&g_sumsq[col], (double)sq);
}

__global__ void finalize_stats_kernel() {
    int c = threadIdx.x;
    if (c < DIM) {
        double mean = g_sum[c] / (double)N_NODES;
        double var  = (g_sumsq[c] - mean * mean * (double)N_NODES) / (double)(N_NODES - 1);
        g_mean[c] = (float)mean;
        g_istd[c] = (float)(1.0 / sqrt(var));
    }
}

__global__ void norm_kernel(float* __restrict__ h) {
    int i = blockIdx.x * blockDim.x + threadIdx.x;
    int total = N_NODES * DIM / 4;
    if (i < total) {
        float4 v = ((float4*)h)[i];
        int c = (i * 4) & 127;
        v.x = (v.x - g_mean[c + 0]) * g_istd[c + 0];
        v.y = (v.y - g_mean[c + 1]) * g_istd[c + 1];
        v.z = (v.z - g_mean[c + 2]) * g_istd[c + 2];
        v.w = (v.w - g_mean[c + 3]) * g_istd[c + 3];
        ((float4*)h)[i] = v;
    }
}

// ---------------- launch ----------------
extern "C" void kernel_launch(void* const* d_in, const int* in_sizes, int n_in,
                              void* d_out, int out_size)
{
    const float* feat1 = (const float*)d_in[0];
    const float* feat2 = (const float*)d_in[1];
    const float* W1    = (const float*)d_in[2];
    const float* b1    = (const float*)d_in[3];
    const float* W2    = (const float*)d_in[4];
    const float* b2    = (const float*)d_in[5];
    const int*   src1  = (const int*)d_in[6];
    const int*   dst1  = (const int*)d_in[7];
    const int*   src2  = (const int*)d_in[8];
    const int*   dst2  = (const int*)d_in[9];
    float* out = (float*)d_out;

    cudaFuncSetAttribute(gemm_scale_kernel,
                         cudaFuncAttributeMaxDynamicSharedMemorySize, GEMM_SMEM);

    float* p_xw = nullptr; float* p_h = nullptr;
    cudaGetSymbolAddress((void**)&p_xw, g_xw);
    cudaGetSymbolAddress((void**)&p_h,  g_h);

    const int NB_N = (N_NODES + 255) / 256;
    const int NB_E = (N_EDGES + 255) / 256;
    const int NB_AGG = (N_NODES * 32 + 255) / 256;   // warp per node
    const int NB_NORM = (N_NODES * DIM / 4 + 255) / 256;

    for (int g = 0; g < 2; g++) {
        const float* feat = g ? feat2 : feat1;
        const int*   src  = g ? src2  : src1;
        const int*   dst  = g ? dst2  : dst1;
        float* hout = out + (size_t)g * N_NODES * DIM;

        // build degrees + CSR for this graph
        zero_deg_kernel<<<NB_N, 256>>>();
        degree_kernel<<<NB_E, 256>>>(src, dst);
        scale_kernel<<<NB_N, 256>>>();
        scan_kernel<<<1, 1024>>>();
        scatter_kernel<<<NB_E, 256>>>(src, dst);

        // layer 1: relu( Agg( (x*sout) @ W1 ) * sin + b1 )
        gemm_scale_kernel<<<GEMM_BLOCKS, 256, GEMM_SMEM>>>(feat, W1, p_xw);
        agg_kernel<<<NB_AGG, 256>>>(p_xw, b1, p_h, 1);

        // layer 2: Agg( (h*sout) @ W2 ) * sin + b2  -> d_out half
        gemm_scale_kernel<<<GEMM_BLOCKS, 256, GEMM_SMEM>>>(p_h, W2, p_xw);
        agg_kernel<<<NB_AGG, 256>>>(p_xw, b2, hout, 0);

        // z-score this half in place
        zero_stats_kernel<<<1, 128>>>();
        stats_kernel<<<592, 128>>>(hout);
        finalize_stats_kernel<<<1, 128>>>();
        norm_kernel<<<NB_NORM, 256>>>(hout);
    }
}

// round 2
// speedup vs baseline: 4.8856x; 4.8856x over previous
#include <cuda_runtime.h>
#include <math.h>

#define N_NODES 100000
#define N_EDGES 800000
#define DIM 128
#define TWO_N (2 * N_NODES)
#define TWO_E (2 * N_EDGES)
#define NCHUNK ((TWO_N + 1023) / 1024)   // 196

// ---------------- scratch (no cudaMalloc allowed) ----------------
__device__ float  g_xw[TWO_N * DIM];     // GEMM output / aggregation input (both graphs)
__device__ float  g_h [TWO_N * DIM];     // hidden layer output (both graphs)
__device__ int    g_deg_out[TWO_N];
__device__ int    g_deg_in [TWO_N];
__device__ float  g_sout[TWO_N];
__device__ float  g_sin [TWO_N];
__device__ int    g_rowptr[TWO_N + 1];
__device__ int    g_cursor[TWO_N];
__device__ int    g_cols[TWO_E];         // global src node ids grouped by global dst
__device__ int    g_partials[NCHUNK];
__device__ int    g_pprefix [NCHUNK];
__device__ double g_sum  [2 * DIM];
__device__ double g_sumsq[2 * DIM];
__device__ float  g_mean[2 * DIM];
__device__ float  g_istd[2 * DIM];

// ---------------- packed f32x2 helpers ----------------
typedef unsigned long long u64;

__device__ __forceinline__ u64 ffma2(u64 a, u64 b, u64 c) {
    u64 d;
    asm("fma.rn.f32x2 %0, %1, %2, %3;" : "=l"(d) : "l"(a), "l"(b), "l"(c));
    return d;
}
__device__ __forceinline__ u64 pack2(float x) {
    u64 d; asm("mov.b64 %0, {%1, %1};" : "=l"(d) : "f"(x)); return d;
}
__device__ __forceinline__ u64 packab(float a, float b) {
    u64 d; asm("mov.b64 %0, {%1, %2};" : "=l"(d) : "f"(a), "f"(b)); return d;
}
__device__ __forceinline__ void unpack2(u64 v, float& a, float& b) {
    asm("mov.b64 {%0, %1}, %2;" : "=f"(a), "=f"(b) : "l"(v));
}

// ---------------- build kernels ----------------
__global__ void zero_deg_kernel() {
    int i = blockIdx.x * blockDim.x + threadIdx.x;
    if (i < TWO_N) { g_deg_out[i] = 0; g_deg_in[i] = 0; }
}

__global__ void degree_kernel(const int* __restrict__ src1, const int* __restrict__ dst1,
                              const int* __restrict__ src2, const int* __restrict__ dst2) {
    int i = blockIdx.x * blockDim.x + threadIdx.x;
    if (i < TWO_E) {
        int s, d;
        if (i < N_EDGES) { s = src1[i];           d = dst1[i]; }
        else             { s = src2[i - N_EDGES] + N_NODES; d = dst2[i - N_EDGES] + N_NODES; }
        atomicAdd(&g_deg_out[s], 1);
        atomicAdd(&g_deg_in [d], 1);
    }
}

__global__ void scale_kernel() {
    int i = blockIdx.x * blockDim.x + threadIdx.x;
    if (i < TWO_N) {
        int dout = g_deg_out[i]; if (dout < 1) dout = 1;
        int din  = g_deg_in [i]; if (din  < 1) din  = 1;
        g_sout[i] = rsqrtf((float)dout);
        g_sin [i] = rsqrtf((float)din);
    }
}

// ---------------- parallel 3-pass exclusive scan of g_deg_in -> g_rowptr ----------------
__device__ __forceinline__ int block_incl_scan256(int v) {
    int lane = threadIdx.x & 31, w = threadIdx.x >> 5;
    #pragma unroll
    for (int off = 1; off < 32; off <<= 1) {
        int t = __shfl_up_sync(0xffffffffu, v, off);
        if (lane >= off) v += t;
    }
    __shared__ int ws[8];
    if (lane == 31) ws[w] = v;
    __syncthreads();
    if (w == 0 && lane < 8) {
        int x = ws[lane];
        #pragma unroll
        for (int off = 1; off < 8; off <<= 1) {
            int t = __shfl_up_sync(0xffu, x, off);
            if (lane >= off) x += t;
        }
        ws[lane] = x;
    }
    __syncthreads();
    if (w > 0) v += ws[w - 1];
    return v;
}

__global__ void scan_partial_kernel() {
    int base = blockIdx.x * 1024 + threadIdx.x * 4;
    int s = 0;
    #pragma unroll
    for (int j = 0; j < 4; j++) { int i = base + j; if (i < TWO_N) s += g_deg_in[i]; }
    __shared__ int red[256];
    red[threadIdx.x] = s; __syncthreads();
    #pragma unroll
    for (int off = 128; off > 0; off >>= 1) {
        if (threadIdx.x < off) red[threadIdx.x] += red[threadIdx.x + off];
        __syncthreads();
    }
    if (threadIdx.x == 0) g_partials[blockIdx.x] = red[0];
}

__global__ void scan_mid_kernel() {
    int t = threadIdx.x;
    int v = (t < NCHUNK) ? g_partials[t] : 0;
    int incl = block_incl_scan256(v);
    if (t < NCHUNK) g_pprefix[t] = incl - v;
    if (t == 0) g_rowptr[TWO_N] = TWO_E;
}

__global__ void scan_final_kernel() {
    int base = blockIdx.x * 1024 + threadIdx.x * 4;
    int d[4]; int s = 0;
    #pragma unroll
    for (int j = 0; j < 4; j++) { int i = base + j; d[j] = (i < TWO_N) ? g_deg_in[i] : 0; s += d[j]; }
    int incl = block_incl_scan256(s);
    int excl = incl - s + g_pprefix[blockIdx.x];
    #pragma unroll
    for (int j = 0; j < 4; j++) {
        int i = base + j;
        if (i < TWO_N) { g_rowptr[i] = excl; g_cursor[i] = excl; excl += d[j]; }
    }
}

__global__ void scatter_kernel(const int* __restrict__ src1, const int* __restrict__ dst1,
                               const int* __restrict__ src2, const int* __restrict__ dst2) {
    int i = blockIdx.x * blockDim.x + threadIdx.x;
    if (i < TWO_E) {
        int s, d;
        if (i < N_EDGES) { s = src1[i];           d = dst1[i]; }
        else             { s = src2[i - N_EDGES] + N_NODES; d = dst2[i - N_EDGES] + N_NODES; }
        int p = atomicAdd(&g_cursor[d], 1);
        g_cols[p] = s;
    }
}

// ---------------- GEMM: Y[row] = (X[row] * g_sout[row]) @ W over both graphs ----------------
// Tile 64 rows x 128 cols. 256 threads: warp w -> rows w*8..w*8+7, lane -> cols lane*4..+3.
// W loads are 512B contiguous per warp (conflict-free); X loads warp-broadcast.
#define TILE_R 64
#define GEMM_BLOCKS 296
#define GEMM_SMEM ((DIM * DIM + TILE_R * DIM) * (int)sizeof(float))

__global__ void __launch_bounds__(256) gemm_kernel(
    const float* __restrict__ X0, const float* __restrict__ X1,
    const float* __restrict__ W, float* __restrict__ Y)
{
    extern __shared__ float smem[];
    float* Ws = smem;                   // [128][128]
    float* Xs = smem + DIM * DIM;       // [64][128]

    for (int i = threadIdx.x * 4; i < DIM * DIM; i += 256 * 4)
        *(float4*)&Ws[i] = *(const float4*)&W[i];

    int warp = threadIdx.x >> 5;
    int lane = threadIdx.x & 31;
    const int ntiles = TWO_N / TILE_R;  // 3125 exact

    for (int tile = blockIdx.x; tile < ntiles; tile += gridDim.x) {
        int row0 = tile * TILE_R;
        __syncthreads();
        for (int idx = threadIdx.x * 4; idx < TILE_R * DIM; idx += 1024) {
            int rr = idx >> 7, kk = idx & 127;
            int grow = row0 + rr;
            const float* Xp = (grow < N_NODES) ? (X0 + (size_t)grow * DIM)
                                               : (X1 + (size_t)(grow - N_NODES) * DIM);
            float4 xv = *(const float4*)&Xp[kk];
            float s = g_sout[grow];
            xv.x *= s; xv.y *= s; xv.z *= s; xv.w *= s;
            *(float4*)&Xs[rr * DIM + kk] = xv;
        }
        __syncthreads();

        u64 acc[8][2];
        #pragma unroll
        for (int i = 0; i < 8; i++) { acc[i][0] = 0ull; acc[i][1] = 0ull; }

        const float* xrow = &Xs[(warp * 8) * DIM];
        #pragma unroll 2
        for (int k = 0; k < DIM; k += 4) {
            u64 w0l, w0h, w1l, w1h, w2l, w2h, w3l, w3h;
            {
                float4 w0 = *(float4*)&Ws[(k + 0) * DIM + lane * 4];
                float4 w1 = *(float4*)&Ws[(k + 1) * DIM + lane * 4];
                float4 w2 = *(float4*)&Ws[(k + 2) * DIM + lane * 4];
                float4 w3 = *(float4*)&Ws[(k + 3) * DIM + lane * 4];
                w0l = packab(w0.x, w0.y); w0h = packab(w0.z, w0.w);
                w1l = packab(w1.x, w1.y); w1h = packab(w1.z, w1.w);
                w2l = packab(w2.x, w2.y); w2h = packab(w2.z, w2.w);
                w3l = packab(w3.x, w3.y); w3h = packab(w3.z, w3.w);
            }
            #pragma unroll
            for (int i = 0; i < 8; i++) {
                float4 xv = *(float4*)&xrow[i * DIM + k];
                u64 a0 = pack2(xv.x), a1 = pack2(xv.y), a2 = pack2(xv.z), a3 = pack2(xv.w);
                acc[i][0] = ffma2(a0, w0l, acc[i][0]);
                acc[i][1] = ffma2(a0, w0h, acc[i][1]);
                acc[i][0] = ffma2(a1, w1l, acc[i][0]);
                acc[i][1] = ffma2(a1, w1h, acc[i][1]);
                acc[i][0] = ffma2(a2, w2l, acc[i][0]);
                acc[i][1] = ffma2(a2, w2h, acc[i][1]);
                acc[i][0] = ffma2(a3, w3l, acc[i][0]);
                acc[i][1] = ffma2(a3, w3h, acc[i][1]);
            }
        }

        #pragma unroll
        for (int i = 0; i < 8; i++) {
            float4 o;
            unpack2(acc[i][0], o.x, o.y);
            unpack2(acc[i][1], o.z, o.w);
            int grow = row0 + warp * 8 + i;
            *(float4*)&Y[(size_t)grow * DIM + lane * 4] = o;
        }
    }
}

// ---------------- CSR aggregation (both graphs): warp per dst node ----------------
__global__ void agg_kernel(const float* __restrict__ Xw,
                           const float* __restrict__ bias,
                           float* __restrict__ out, int do_relu)
{
    int warp = (blockIdx.x * blockDim.x + threadIdx.x) >> 5;
    int lane = threadIdx.x & 31;
    if (warp >= TWO_N) return;
    int r0 = g_rowptr[warp];
    int r1 = g_rowptr[warp + 1];
    float4 acc = make_float4(0.f, 0.f, 0.f, 0.f);
    for (int e = r0; e < r1; e++) {
        int csrc = g_cols[e];
        float4 v = *(const float4*)&Xw[(size_t)csrc * DIM + lane * 4];
        acc.x += v.x; acc.y += v.y; acc.z += v.z; acc.w += v.w;
    }
    float s = g_sin[warp];
    float4 b = *(const float4*)&bias[lane * 4];
    float4 o;
    o.x = acc.x * s + b.x; o.y = acc.y * s + b.y;
    o.z = acc.z * s + b.z; o.w = acc.w * s + b.w;
    if (do_relu) {
        o.x = fmaxf(o.x, 0.f); o.y = fmaxf(o.y, 0.f);
        o.z = fmaxf(o.z, 0.f); o.w = fmaxf(o.w, 0.f);
    }
    *(float4*)&out[(size_t)warp * DIM + lane * 4] = o;
}

// ---------------- column stats + z-score ----------------
__global__ void zero_stats_kernel() {
    int i = threadIdx.x;
    if (i < 2 * DIM) { g_sum[i] = 0.0; g_sumsq[i] = 0.0; }
}

__global__ void stats_kernel(const float* __restrict__ h_all) {
    int col = threadIdx.x;               // blockDim = 128
    int graph = blockIdx.y;
    const float* h = h_all + (size_t)graph * N_NODES * DIM;
    float sum = 0.f, sq = 0.f;
    for (int row = blockIdx.x; row < N_NODES; row += gridDim.x) {
        float v = h[(size_t)row * DIM + col];
        sum += v; sq += v * v;
    }
    atomicAdd(&g_sum  [graph * DIM + col], (double)sum);
    atomicAdd(&g_sumsq[graph * DIM + col], (double)sq);
}

__global__ void finalize_stats_kernel() {
    int c = threadIdx.x;
    if (c < 2 * DIM) {
        double mean = g_sum[c] / (double)N_NODES;
        double var  = (g_sumsq[c] - mean * mean * (double)N_NODES) / (double)(N_NODES - 1);
        g_mean[c] = (float)mean;
        g_istd[c] = (float)(1.0 / sqrt(var));
    }
}

__global__ void norm_kernel(float* __restrict__ h) {
    int i = blockIdx.x * blockDim.x + threadIdx.x;
    const int total = TWO_N * DIM / 4;
    if (i < total) {
        float4 v = ((float4*)h)[i];
        int c = (i * 4) & 127;
        int graph = (i >= N_NODES * DIM / 4) ? 1 : 0;
        int m = graph * DIM + c;
        v.x = (v.x - g_mean[m + 0]) * g_istd[m + 0];
        v.y = (v.y - g_mean[m + 1]) * g_istd[m + 1];
        v.z = (v.z - g_mean[m + 2]) * g_istd[m + 2];
        v.w = (v.w - g_mean[m + 3]) * g_istd[m + 3];
        ((float4*)h)[i] = v;
    }
}

// ---------------- launch ----------------
extern "C" void kernel_launch(void* const* d_in, const int* in_sizes, int n_in,
                              void* d_out, int out_size)
{
    const float* feat1 = (const float*)d_in[0];
    const float* feat2 = (const float*)d_in[1];
    const float* W1    = (const float*)d_in[2];
    const float* b1    = (const float*)d_in[3];
    const float* W2    = (const float*)d_in[4];
    const float* b2    = (const float*)d_in[5];
    const int*   src1  = (const int*)d_in[6];
    const int*   dst1  = (const int*)d_in[7];
    const int*   src2  = (const int*)d_in[8];
    const int*   dst2  = (const int*)d_in[9];
    float* out = (float*)d_out;

    static bool configured = false;
    cudaFuncSetAttribute(gemm_kernel,
                         cudaFuncAttributeMaxDynamicSharedMemorySize, GEMM_SMEM);
    (void)configured;

    float* p_xw = nullptr; float* p_h = nullptr;
    cudaGetSymbolAddress((void**)&p_xw, g_xw);
    cudaGetSymbolAddress((void**)&p_h,  g_h);

    const int NB_2N  = (TWO_N + 255) / 256;
    const int NB_2E  = (TWO_E + 255) / 256;
    const int NB_AGG = (TWO_N * 32 + 255) / 256;
    const int NB_NORM = (TWO_N * DIM / 4 + 255) / 256;

    // graph structure (both graphs at once)
    zero_deg_kernel<<<NB_2N, 256>>>();
    degree_kernel<<<NB_2E, 256>>>(src1, dst1, src2, dst2);
    scale_kernel<<<NB_2N, 256>>>();
    scan_partial_kernel<<<NCHUNK, 256>>>();
    scan_mid_kernel<<<1, 256>>>();
    scan_final_kernel<<<NCHUNK, 256>>>();
    scatter_kernel<<<NB_2E, 256>>>(src1, dst1, src2, dst2);

    // layer 1 (both graphs): relu( Agg((x*sout)@W1) * sin + b1 )
    gemm_kernel<<<GEMM_BLOCKS, 256, GEMM_SMEM>>>(feat1, feat2, W1, p_xw);
    agg_kernel<<<NB_AGG, 256>>>(p_xw, b1, p_h, 1);

    // layer 2 (both graphs): Agg((h*sout)@W2) * sin + b2 -> d_out
    gemm_kernel<<<GEMM_BLOCKS, 256, GEMM_SMEM>>>(p_h, p_h + (size_t)N_NODES * DIM, W2, p_xw);
    agg_kernel<<<NB_AGG, 256>>>(p_xw, b2, out, 0);

    // z-score both halves
    zero_stats_kernel<<<1, 256>>>();
    stats_kernel<<<dim3(592, 2), 128>>>(out);
    finalize_stats_kernel<<<1, 256>>>();
    norm_kernel<<<NB_NORM, 256>>>(out);
}

// round 3
// speedup vs baseline: 5.2349x; 1.0715x over previous
#include <cuda_runtime.h>
#include <cuda_fp16.h>
#include <math.h>

#define N_NODES 100000
#define N_EDGES 800000
#define DIM 128
#define TWO_N (2 * N_NODES)
#define TWO_E (2 * N_EDGES)
#define NCHUNK ((TWO_N + 1023) / 1024)   // 196

// ---------------- scratch (no cudaMalloc allowed) ----------------
__device__ __half g_xw[TWO_N * DIM];     // GEMM output (fp16) / aggregation input
__device__ float  g_h [TWO_N * DIM];     // hidden layer output (fp32)
__device__ int    g_deg_out[TWO_N];
__device__ int    g_deg_in [TWO_N];
__device__ float  g_sout[TWO_N];
__device__ float  g_sin [TWO_N];
__device__ int    g_rowptr[TWO_N + 1];
__device__ int    g_cursor[TWO_N];
__device__ int    g_cols[TWO_E];
__device__ int    g_partials[NCHUNK];
__device__ int    g_pprefix [NCHUNK];
__device__ double g_sum  [2 * DIM];
__device__ double g_sumsq[2 * DIM];
__device__ float  g_mean[2 * DIM];
__device__ float  g_istd[2 * DIM];

// ---------------- packed f32x2 helpers ----------------
typedef unsigned long long u64;

__device__ __forceinline__ u64 ffma2(u64 a, u64 b, u64 c) {
    u64 d;
    asm("fma.rn.f32x2 %0, %1, %2, %3;" : "=l"(d) : "l"(a), "l"(b), "l"(c));
    return d;
}
__device__ __forceinline__ u64 packab(float a, float b) {
    u64 d; asm("mov.b64 %0, {%1, %2};" : "=l"(d) : "f"(a), "f"(b)); return d;
}
__device__ __forceinline__ void unpack2(u64 v, float& a, float& b) {
    asm("mov.b64 {%0, %1}, %2;" : "=f"(a), "=f"(b) : "l"(v));
}

// ---------------- build kernels ----------------
__global__ void zero_kernel() {
    int i = blockIdx.x * blockDim.x + threadIdx.x;
    if (i < TWO_N) { g_deg_out[i] = 0; g_deg_in[i] = 0; }
    if (i < 2 * DIM) { g_sum[i] = 0.0; g_sumsq[i] = 0.0; }
}

__global__ void degree_kernel(const int* __restrict__ src1, const int* __restrict__ dst1,
                              const int* __restrict__ src2, const int* __restrict__ dst2) {
    int i = blockIdx.x * blockDim.x + threadIdx.x;
    if (i < TWO_E) {
        int s, d;
        if (i < N_EDGES) { s = src1[i];                     d = dst1[i]; }
        else             { s = src2[i - N_EDGES] + N_NODES; d = dst2[i - N_EDGES] + N_NODES; }
        atomicAdd(&g_deg_out[s], 1);
        atomicAdd(&g_deg_in [d], 1);
    }
}

// ---------------- parallel 3-pass exclusive scan of g_deg_in -> g_rowptr ----------------
__device__ __forceinline__ int block_incl_scan256(int v) {
    int lane = threadIdx.x & 31, w = threadIdx.x >> 5;
    #pragma unroll
    for (int off = 1; off < 32; off <<= 1) {
        int t = __shfl_up_sync(0xffffffffu, v, off);
        if (lane >= off) v += t;
    }
    __shared__ int ws[8];
    if (lane == 31) ws[w] = v;
    __syncthreads();
    if (w == 0 && lane < 8) {
        int x = ws[lane];
        #pragma unroll
        for (int off = 1; off < 8; off <<= 1) {
            int t = __shfl_up_sync(0xffu, x, off);
            if (lane >= off) x += t;
        }
        ws[lane] = x;
    }
    __syncthreads();
    if (w > 0) v += ws[w - 1];
    return v;
}

// also computes sout/sin (fused former scale_kernel)
__global__ void scan_partial_kernel() {
    int base = blockIdx.x * 1024 + threadIdx.x * 4;
    int s = 0;
    #pragma unroll
    for (int j = 0; j < 4; j++) {
        int i = base + j;
        if (i < TWO_N) {
            int din = g_deg_in[i];
            s += din;
            int dout = g_deg_out[i]; if (dout < 1) dout = 1;
            if (din < 1) din = 1;
            g_sout[i] = rsqrtf((float)dout);
            g_sin [i] = rsqrtf((float)din);
        }
    }
    __shared__ int red[256];
    red[threadIdx.x] = s; __syncthreads();
    #pragma unroll
    for (int off = 128; off > 0; off >>= 1) {
        if (threadIdx.x < off) red[threadIdx.x] += red[threadIdx.x + off];
        __syncthreads();
    }
    if (threadIdx.x == 0) g_partials[blockIdx.x] = red[0];
}

__global__ void scan_mid_kernel() {
    int t = threadIdx.x;
    int v = (t < NCHUNK) ? g_partials[t] : 0;
    int incl = block_incl_scan256(v);
    if (t < NCHUNK) g_pprefix[t] = incl - v;
    if (t == 0) g_rowptr[TWO_N] = TWO_E;
}

__global__ void scan_final_kernel() {
    int base = blockIdx.x * 1024 + threadIdx.x * 4;
    int d[4]; int s = 0;
    #pragma unroll
    for (int j = 0; j < 4; j++) { int i = base + j; d[j] = (i < TWO_N) ? g_deg_in[i] : 0; s += d[j]; }
    int incl = block_incl_scan256(s);
    int excl = incl - s + g_pprefix[blockIdx.x];
    #pragma unroll
    for (int j = 0; j < 4; j++) {
        int i = base + j;
        if (i < TWO_N) { g_rowptr[i] = excl; g_cursor[i] = excl; excl += d[j]; }
    }
}

__global__ void scatter_kernel(const int* __restrict__ src1, const int* __restrict__ dst1,
                               const int* __restrict__ src2, const int* __restrict__ dst2) {
    int i = blockIdx.x * blockDim.x + threadIdx.x;
    if (i < TWO_E) {
        int s, d;
        if (i < N_EDGES) { s = src1[i];                     d = dst1[i]; }
        else             { s = src2[i - N_EDGES] + N_NODES; d = dst2[i - N_EDGES] + N_NODES; }
        int p = atomicAdd(&g_cursor[d], 1);
        g_cols[p] = s;
    }
}

// ---------------- GEMM: Yh[row] = half( (X[row] * g_sout[row]) @ W ) ----------------
// Tile 64 rows x 128 cols, 256 threads. W transposed in smem (pitch 132, conflict-free
// LDS.128 with col map c = lane + 32*cc). f32x2 pairs over k: both operands come
// directly from LDS.128 register quads -> no duplication movs.
#define TILE_R 64
#define WT_PITCH 132
#define GEMM_BLOCKS 296
#define GEMM_SMEM ((DIM * WT_PITCH + TILE_R * DIM) * (int)sizeof(float))

__global__ void __launch_bounds__(256) gemm_kernel(
    const float* __restrict__ X0, const float* __restrict__ X1,
    const float* __restrict__ W, __half* __restrict__ Yh)
{
    extern __shared__ float smem[];
    float* WT = smem;                        // [128][132] transposed
    float* Xs = smem + DIM * WT_PITCH;       // [64][128]

    // stage W transposed
    for (int idx = threadIdx.x * 4; idx < DIM * DIM; idx += 256 * 4) {
        int k = idx >> 7, c = idx & 127;
        float4 w = *(const float4*)&W[idx];
        WT[(c + 0) * WT_PITCH + k] = w.x;
        WT[(c + 1) * WT_PITCH + k] = w.y;
        WT[(c + 2) * WT_PITCH + k] = w.z;
        WT[(c + 3) * WT_PITCH + k] = w.w;
    }

    int warp = threadIdx.x >> 5;
    int lane = threadIdx.x & 31;
    const int ntiles = TWO_N / TILE_R;       // 3125 exact

    for (int tile = blockIdx.x; tile < ntiles; tile += gridDim.x) {
        int row0 = tile * TILE_R;
        __syncthreads();
        for (int idx = threadIdx.x * 4; idx < TILE_R * DIM; idx += 1024) {
            int rr = idx >> 7, kk = idx & 127;
            int grow = row0 + rr;
            const float* Xp = (grow < N_NODES) ? (X0 + (size_t)grow * DIM)
                                               : (X1 + (size_t)(grow - N_NODES) * DIM);
            float4 xv = *(const float4*)&Xp[kk];
            float s = g_sout[grow];
            xv.x *= s; xv.y *= s; xv.z *= s; xv.w *= s;
            *(float4*)&Xs[rr * DIM + kk] = xv;
        }
        __syncthreads();

        u64 acc[8][4];
        #pragma unroll
        for (int i = 0; i < 8; i++)
            #pragma unroll
            for (int c = 0; c < 4; c++) acc[i][c] = 0ull;

        const float* xbase = &Xs[(warp * 8) * DIM];
        #pragma unroll 4
        for (int k = 0; k < DIM; k += 4) {
            u64 w01[4], w23[4];
            #pragma unroll
            for (int cc = 0; cc < 4; cc++) {
                float4 wv = *(float4*)&WT[(lane + 32 * cc) * WT_PITCH + k];
                w01[cc] = packab(wv.x, wv.y);
                w23[cc] = packab(wv.z, wv.w);
            }
            #pragma unroll
            for (int i = 0; i < 8; i++) {
                float4 xv = *(float4*)&xbase[i * DIM + k];
                u64 x01 = packab(xv.x, xv.y);
                u64 x23 = packab(xv.z, xv.w);
                #pragma unroll
                for (int cc = 0; cc < 4; cc++) {
                    acc[i][cc] = ffma2(x01, w01[cc], acc[i][cc]);
                    acc[i][cc] = ffma2(x23, w23[cc], acc[i][cc]);
                }
            }
        }

        #pragma unroll
        for (int i = 0; i < 8; i++) {
            int grow = row0 + warp * 8 + i;
            __half* yp = &Yh[(size_t)grow * DIM];
            #pragma unroll
            for (int cc = 0; cc < 4; cc++) {
                float lo, hi;
                unpack2(acc[i][cc], lo, hi);
                yp[lane + 32 * cc] = __float2half_rn(lo + hi);
            }
        }
    }
}

// ---------------- CSR aggregation: warp per dst node, fp16 gather ----------------
__global__ void agg_kernel(const __half* __restrict__ Xw,
                           const float* __restrict__ bias,
                           float* __restrict__ out, int do_relu)
{
    int warp = (blockIdx.x * blockDim.x + threadIdx.x) >> 5;
    int lane = threadIdx.x & 31;
    if (warp >= TWO_N) return;
    int r0 = g_rowptr[warp];
    int r1 = g_rowptr[warp + 1];
    float4 a0 = make_float4(0.f, 0.f, 0.f, 0.f);
    float4 a1 = make_float4(0.f, 0.f, 0.f, 0.f);
    int e = r0;
    for (; e + 1 < r1; e += 2) {
        int c0 = g_cols[e], c1 = g_cols[e + 1];
        uint2 u0 = *(const uint2*)&Xw[(size_t)c0 * DIM + lane * 4];
        uint2 u1 = *(const uint2*)&Xw[(size_t)c1 * DIM + lane * 4];
        float2 p0 = __half22float2(*(__half2*)&u0.x);
        float2 q0 = __half22float2(*(__half2*)&u0.y);
        float2 p1 = __half22float2(*(__half2*)&u1.x);
        float2 q1 = __half22float2(*(__half2*)&u1.y);
        a0.x += p0.x; a0.y += p0.y; a0.z += q0.x; a0.w += q0.y;
        a1.x += p1.x; a1.y += p1.y; a1.z += q1.x; a1.w += q1.y;
    }
    if (e < r1) {
        int c0 = g_cols[e];
        uint2 u0 = *(const uint2*)&Xw[(size_t)c0 * DIM + lane * 4];
        float2 p0 = __half22float2(*(__half2*)&u0.x);
        float2 q0 = __half22float2(*(__half2*)&u0.y);
        a0.x += p0.x; a0.y += p0.y; a0.z += q0.x; a0.w += q0.y;
    }
    a0.x += a1.x; a0.y += a1.y; a0.z += a1.z; a0.w += a1.w;

    float s = g_sin[warp];
    float4 b = *(const float4*)&bias[lane * 4];
    float4 o;
    o.x = a0.x * s + b.x; o.y = a0.y * s + b.y;
    o.z = a0.z * s + b.z; o.w = a0.w * s + b.w;
    if (do_relu) {
        o.x = fmaxf(o.x, 0.f); o.y = fmaxf(o.y, 0.f);
        o.z = fmaxf(o.z, 0.f); o.w = fmaxf(o.w, 0.f);
    }
    *(float4*)&out[(size_t)warp * DIM + lane * 4] = o;
}

// ---------------- column stats + z-score ----------------
__global__ void stats_kernel(const float* __restrict__ h_all) {
    int col = threadIdx.x;               // blockDim = 128
    int graph = blockIdx.y;
    const float* h = h_all + (size_t)graph * N_NODES * DIM;
    float sum = 0.f, sq = 0.f;
    for (int row = blockIdx.x; row < N_NODES; row += gridDim.x) {
        float v = h[(size_t)row * DIM + col];
        sum += v; sq += v * v;
    }
    atomicAdd(&g_sum  [graph * DIM + col], (double)sum);
    atomicAdd(&g_sumsq[graph * DIM + col], (double)sq);
}

__global__ void finalize_stats_kernel() {
    int c = threadIdx.x;
    if (c < 2 * DIM) {
        double mean = g_sum[c] / (double)N_NODES;
        double var  = (g_sumsq[c] - mean * mean * (double)N_NODES) / (double)(N_NODES - 1);
        g_mean[c] = (float)mean;
        g_istd[c] = (float)(1.0 / sqrt(var));
    }
}

__global__ void norm_kernel(float* __restrict__ h) {
    int i = blockIdx.x * blockDim.x + threadIdx.x;
    const int total = TWO_N * DIM / 4;
    if (i < total) {
        float4 v = ((float4*)h)[i];
        int c = (i * 4) & 127;
        int graph = (i >= N_NODES * DIM / 4) ? 1 : 0;
        int m = graph * DIM + c;
        v.x = (v.x - g_mean[m + 0]) * g_istd[m + 0];
        v.y = (v.y - g_mean[m + 1]) * g_istd[m + 1];
        v.z = (v.z - g_mean[m + 2]) * g_istd[m + 2];
        v.w = (v.w - g_mean[m + 3]) * g_istd[m + 3];
        ((float4*)h)[i] = v;
    }
}

// ---------------- launch ----------------
extern "C" void kernel_launch(void* const* d_in, const int* in_sizes, int n_in,
                              void* d_out, int out_size)
{
    const float* feat1 = (const float*)d_in[0];
    const float* feat2 = (const float*)d_in[1];
    const float* W1    = (const float*)d_in[2];
    const float* b1    = (const float*)d_in[3];
    const float* W2    = (const float*)d_in[4];
    const float* b2    = (const float*)d_in[5];
    const int*   src1  = (const int*)d_in[6];
    const int*   dst1  = (const int*)d_in[7];
    const int*   src2  = (const int*)d_in[8];
    const int*   dst2  = (const int*)d_in[9];
    float* out = (float*)d_out;

    cudaFuncSetAttribute(gemm_kernel,
                         cudaFuncAttributeMaxDynamicSharedMemorySize, GEMM_SMEM);

    __half* p_xw = nullptr; float* p_h = nullptr;
    cudaGetSymbolAddress((void**)&p_xw, g_xw);
    cudaGetSymbolAddress((void**)&p_h,  g_h);

    const int NB_2N  = (TWO_N + 255) / 256;
    const int NB_2E  = (TWO_E + 255) / 256;
    const int NB_AGG = (TWO_N * 32 + 255) / 256;
    const int NB_NORM = (TWO_N * DIM / 4 + 255) / 256;

    // graph structure (both graphs at once)
    zero_kernel<<<NB_2N, 256>>>();
    degree_kernel<<<NB_2E, 256>>>(src1, dst1, src2, dst2);
    scan_partial_kernel<<<NCHUNK, 256>>>();   // also computes sout/sin
    scan_mid_kernel<<<1, 256>>>();
    scan_final_kernel<<<NCHUNK, 256>>>();
    scatter_kernel<<<NB_2E, 256>>>(src1, dst1, src2, dst2);

    // layer 1 (both graphs): relu( Agg((x*sout)@W1) * sin + b1 )
    gemm_kernel<<<GEMM_BLOCKS, 256, GEMM_SMEM>>>(feat1, feat2, W1, p_xw);
    agg_kernel<<<NB_AGG, 256>>>(p_xw, b1, p_h, 1);

    // layer 2 (both graphs): Agg((h*sout)@W2) * sin + b2 -> d_out
    gemm_kernel<<<GEMM_BLOCKS, 256, GEMM_SMEM>>>(p_h, p_h + (size_t)N_NODES * DIM, W2, p_xw);
    agg_kernel<<<NB_AGG, 256>>>(p_xw, b2, out, 0);

    // z-score both halves
    stats_kernel<<<dim3(592, 2), 128>>>(out);
    finalize_stats_kernel<<<1, 256>>>();
    norm_kernel<<<NB_NORM, 256>>>(out);
}

// round 5
// speedup vs baseline: 6.6714x; 1.2744x over previous
#include <cuda_runtime.h>
#include <cuda_fp16.h>
#include <mma.h>
#include <math.h>
#include <stdint.h>

using namespace nvcuda;

#define N_NODES 100000
#define N_EDGES 800000
#define DIM 128
#define TWO_N (2 * N_NODES)
#define TWO_E (2 * N_EDGES)
#define NCHUNK ((TWO_N + 1023) / 1024)   // 196

// ---------------- scratch (no cudaMalloc allowed) ----------------
__device__ __half g_xw[TWO_N * DIM];     // GEMM output (fp16) / aggregation input
__device__ float  g_h [TWO_N * DIM];     // hidden layer output (fp32)
__device__ int    g_deg_out[TWO_N];
__device__ int    g_deg_in [TWO_N];
__device__ float  g_sout[TWO_N];
__device__ float  g_sin [TWO_N];
__device__ int    g_rowptr[TWO_N + 1];
__device__ int    g_cursor[TWO_N];
__device__ int    g_cols[TWO_E];
__device__ int    g_partials[NCHUNK];
__device__ int    g_pprefix [NCHUNK];
__device__ double g_sum  [2 * DIM];
__device__ double g_sumsq[2 * DIM];
__device__ float  g_mean[2 * DIM];
__device__ float  g_istd[2 * DIM];

// ---------------- build kernels ----------------
__global__ void zero_kernel() {
    int i = blockIdx.x * blockDim.x + threadIdx.x;
    if (i < TWO_N) { g_deg_out[i] = 0; g_deg_in[i] = 0; }
    if (i < 2 * DIM) { g_sum[i] = 0.0; g_sumsq[i] = 0.0; }
}

__global__ void degree_kernel(const int* __restrict__ src1, const int* __restrict__ dst1,
                              const int* __restrict__ src2, const int* __restrict__ dst2) {
    int i = blockIdx.x * blockDim.x + threadIdx.x;
    if (i < TWO_E) {
        int s, d;
        if (i < N_EDGES) { s = src1[i];                     d = dst1[i]; }
        else             { s = src2[i - N_EDGES] + N_NODES; d = dst2[i - N_EDGES] + N_NODES; }
        atomicAdd(&g_deg_out[s], 1);
        atomicAdd(&g_deg_in [d], 1);
    }
}

__device__ __forceinline__ int block_incl_scan256(int v) {
    int lane = threadIdx.x & 31, w = threadIdx.x >> 5;
    #pragma unroll
    for (int off = 1; off < 32; off <<= 1) {
        int t = __shfl_up_sync(0xffffffffu, v, off);
        if (lane >= off) v += t;
    }
    __shared__ int ws[8];
    if (lane == 31) ws[w] = v;
    __syncthreads();
    if (w == 0 && lane < 8) {
        int x = ws[lane];
        #pragma unroll
        for (int off = 1; off < 8; off <<= 1) {
            int t = __shfl_up_sync(0xffu, x, off);
            if (lane >= off) x += t;
        }
        ws[lane] = x;
    }
    __syncthreads();
    if (w > 0) v += ws[w - 1];
    return v;
}

// also computes sout/sin (fused scale)
__global__ void scan_partial_kernel() {
    int base = blockIdx.x * 1024 + threadIdx.x * 4;
    int s = 0;
    #pragma unroll
    for (int j = 0; j < 4; j++) {
        int i = base + j;
        if (i < TWO_N) {
            int din = g_deg_in[i];
            s += din;
            int dout = g_deg_out[i]; if (dout < 1) dout = 1;
            if (din < 1) din = 1;
            g_sout[i] = rsqrtf((float)dout);
            g_sin [i] = rsqrtf((float)din);
        }
    }
    __shared__ int red[256];
    red[threadIdx.x] = s; __syncthreads();
    #pragma unroll
    for (int off = 128; off > 0; off >>= 1) {
        if (threadIdx.x < off) red[threadIdx.x] += red[threadIdx.x + off];
        __syncthreads();
    }
    if (threadIdx.x == 0) g_partials[blockIdx.x] = red[0];
}

__global__ void scan_mid_kernel() {
    int t = threadIdx.x;
    int v = (t < NCHUNK) ? g_partials[t] : 0;
    int incl = block_incl_scan256(v);
    if (t < NCHUNK) g_pprefix[t] = incl - v;
    if (t == 0) g_rowptr[TWO_N] = TWO_E;
}

__global__ void scan_final_kernel() {
    int base = blockIdx.x * 1024 + threadIdx.x * 4;
    int d[4]; int s = 0;
    #pragma unroll
    for (int j = 0; j < 4; j++) { int i = base + j; d[j] = (i < TWO_N) ? g_deg_in[i] : 0; s += d[j]; }
    int incl = block_incl_scan256(s);
    int excl = incl - s + g_pprefix[blockIdx.x];
    #pragma unroll
    for (int j = 0; j < 4; j++) {
        int i = base + j;
        if (i < TWO_N) { g_rowptr[i] = excl; g_cursor[i] = excl; excl += d[j]; }
    }
}

__global__ void scatter_kernel(const int* __restrict__ src1, const int* __restrict__ dst1,
                               const int* __restrict__ src2, const int* __restrict__ dst2) {
    int i = blockIdx.x * blockDim.x + threadIdx.x;
    if (i < TWO_E) {
        int s, d;
        if (i < N_EDGES) { s = src1[i];                     d = dst1[i]; }
        else             { s = src2[i - N_EDGES] + N_NODES; d = dst2[i - N_EDGES] + N_NODES; }
        int p = atomicAdd(&g_cursor[d], 1);
        g_cols[p] = s;
    }
}

// ============ wmma GEMM: Yh = half( (X * sout) @ W ), fp16 hi/lo 3-term split ============
// Persistent 148 CTAs x 256 threads (8 warps). Tile 128 rows x 128 cols, K=128.
// smem halves pitch 136 (16B-aligned rows, conflict-benign). W staged once per CTA.
// Epilogue: acc -> fp32 smem (reusing A region) -> fp16 global.
#define LDH 136
#define SM_WHI 0
#define SM_WLO (SM_WHI + 128 * LDH * 2)          // 34816
#define SM_AHI (SM_WLO + 128 * LDH * 2)          // 69632
#define SM_ALO (SM_AHI + 128 * LDH * 2)          // 104448
#define GEMM_SMEM (SM_ALO + 128 * LDH * 2)       // 139264
#define TC_NTILES ((TWO_N + 127) / 128)          // 1563

__global__ void __launch_bounds__(256, 1) gemm_wmma_kernel(
    const float* __restrict__ X0, const float* __restrict__ X1,
    const float* __restrict__ W, __half* __restrict__ Yh)
{
    extern __shared__ __align__(256) char smem[];
    __half* Whi = (__half*)(smem + SM_WHI);
    __half* Wlo = (__half*)(smem + SM_WLO);
    __half* Ahi = (__half*)(smem + SM_AHI);
    __half* Alo = (__half*)(smem + SM_ALO);
    float*  Cout = (float*)(smem + SM_AHI);       // reuse A region after MMA

    int tid = threadIdx.x;
    int warp = tid >> 5;
    int lane = tid & 31;

    // ---- stage W (hi/lo split), once ----
    for (int idx = tid; idx < DIM * DIM; idx += 256) {
        int k = idx >> 7, n = idx & 127;
        float w = W[idx];
        __half hi = __float2half_rn(w);
        __half lo = __float2half_rn(w - __half2float(hi));
        Whi[k * LDH + n] = hi;
        Wlo[k * LDH + n] = lo;
    }
    __syncthreads();

    int r  = tid >> 1;            // row within tile (0..127)
    int kh = (tid & 1) * 64;      // k-half

    for (int tile = blockIdx.x; tile < TC_NTILES; tile += gridDim.x) {
        int row0 = tile * 128;
        __syncthreads();   // epilogue reads of Cout done before A overwrite

        // ---- stage A tile (scaled, hi/lo split) ----
        {
            int grow = row0 + r;
            if (grow < TWO_N) {
                const float* Xp = (grow < N_NODES) ? (X0 + (size_t)grow * DIM)
                                                   : (X1 + (size_t)(grow - N_NODES) * DIM);
                float s = g_sout[grow];
                #pragma unroll
                for (int j = 0; j < 16; j++) {
                    int c = kh + j * 4;
                    float4 xv = *(const float4*)&Xp[c];
                    xv.x *= s; xv.y *= s; xv.z *= s; xv.w *= s;
                    __half h0 = __float2half_rn(xv.x);
                    __half h1 = __float2half_rn(xv.y);
                    __half h2 = __float2half_rn(xv.z);
                    __half h3 = __float2half_rn(xv.w);
                    __half2 hp0 = __halves2half2(h0, h1);
                    __half2 hp1 = __halves2half2(h2, h3);
                    __half2 lp0 = __halves2half2(
                        __float2half_rn(xv.x - __half2float(h0)),
                        __float2half_rn(xv.y - __half2float(h1)));
                    __half2 lp1 = __halves2half2(
                        __float2half_rn(xv.z - __half2float(h2)),
                        __float2half_rn(xv.w - __half2float(h3)));
                    uint2 hv, lv;
                    hv.x = *(uint32_t*)&hp0; hv.y = *(uint32_t*)&hp1;
                    lv.x = *(uint32_t*)&lp0; lv.y = *(uint32_t*)&lp1;
                    *(uint2*)&Ahi[r * LDH + c] = hv;
                    *(uint2*)&Alo[r * LDH + c] = lv;
                }
            } else {
                #pragma unroll
                for (int j = 0; j < 16; j++) {
                    int c = kh + j * 4;
                    *(uint2*)&Ahi[r * LDH + c] = make_uint2(0u, 0u);
                    *(uint2*)&Alo[r * LDH + c] = make_uint2(0u, 0u);
                }
            }
        }
        __syncthreads();

        // ---- MMA: warp computes rows warp*16..+15, all 128 cols ----
        wmma::fragment<wmma::accumulator, 16, 16, 16, float> acc[8];
        #pragma unroll
        for (int n = 0; n < 8; n++) wmma::fill_fragment(acc[n], 0.0f);

        #pragma unroll
        for (int kk = 0; kk < 8; kk++) {
            wmma::fragment<wmma::matrix_a, 16, 16, 16, __half, wmma::row_major> ahi, alo;
            wmma::load_matrix_sync(ahi, &Ahi[(warp * 16) * LDH + kk * 16], LDH);
            wmma::load_matrix_sync(alo, &Alo[(warp * 16) * LDH + kk * 16], LDH);
            #pragma unroll
            for (int n = 0; n < 8; n++) {
                wmma::fragment<wmma::matrix_b, 16, 16, 16, __half, wmma::row_major> bhi, blo;
                wmma::load_matrix_sync(bhi, &Whi[(kk * 16) * LDH + n * 16], LDH);
                wmma::load_matrix_sync(blo, &Wlo[(kk * 16) * LDH + n * 16], LDH);
                wmma::mma_sync(acc[n], ahi, bhi, acc[n]);
                wmma::mma_sync(acc[n], ahi, blo, acc[n]);
                wmma::mma_sync(acc[n], alo, bhi, acc[n]);
            }
        }
        __syncthreads();   // all A reads done; Cout may overwrite A region

        // ---- epilogue: per-warp fp32 smem staging -> fp16 global ----
        #pragma unroll
        for (int n = 0; n < 8; n++)
            wmma::store_matrix_sync(&Cout[(warp * 16) * 128 + n * 16], acc[n], 128,
                                    wmma::mem_row_major);
        __syncwarp();

        #pragma unroll
        for (int rr = 0; rr < 16; rr++) {
            int grow = row0 + warp * 16 + rr;
            if (grow < TWO_N) {
                float4 v = *(float4*)&Cout[(warp * 16 + rr) * 128 + lane * 4];
                __half2 a = __floats2half2_rn(v.x, v.y);
                __half2 b = __floats2half2_rn(v.z, v.w);
                uint2 o; o.x = *(uint32_t*)&a; o.y = *(uint32_t*)&b;
                *(uint2*)&Yh[(size_t)grow * DIM + lane * 4] = o;
            }
        }
    }
}

// ---------------- CSR aggregation: warp per dst node, fp16 gather ----------------
__global__ void agg_kernel(const __half* __restrict__ Xw,
                           const float* __restrict__ bias,
                           float* __restrict__ out, int do_relu)
{
    int warp = (blockIdx.x * blockDim.x + threadIdx.x) >> 5;
    int lane = threadIdx.x & 31;
    if (warp >= TWO_N) return;
    int r0 = g_rowptr[warp];
    int r1 = g_rowptr[warp + 1];
    float4 a0 = make_float4(0.f, 0.f, 0.f, 0.f);
    float4 a1 = make_float4(0.f, 0.f, 0.f, 0.f);
    int e = r0;
    for (; e + 1 < r1; e += 2) {
        int c0 = g_cols[e], c1 = g_cols[e + 1];
        uint2 u0 = *(const uint2*)&Xw[(size_t)c0 * DIM + lane * 4];
        uint2 u1 = *(const uint2*)&Xw[(size_t)c1 * DIM + lane * 4];
        float2 p0 = __half22float2(*(__half2*)&u0.x);
        float2 q0 = __half22float2(*(__half2*)&u0.y);
        float2 p1 = __half22float2(*(__half2*)&u1.x);
        float2 q1 = __half22float2(*(__half2*)&u1.y);
        a0.x += p0.x; a0.y += p0.y; a0.z += q0.x; a0.w += q0.y;
        a1.x += p1.x; a1.y += p1.y; a1.z += q1.x; a1.w += q1.y;
    }
    if (e < r1) {
        int c0 = g_cols[e];
        uint2 u0 = *(const uint2*)&Xw[(size_t)c0 * DIM + lane * 4];
        float2 p0 = __half22float2(*(__half2*)&u0.x);
        float2 q0 = __half22float2(*(__half2*)&u0.y);
        a0.x += p0.x; a0.y += p0.y; a0.z += q0.x; a0.w += q0.y;
    }
    a0.x += a1.x; a0.y += a1.y; a0.z += a1.z; a0.w += a1.w;

    float s = g_sin[warp];
    float4 b = *(const float4*)&bias[lane * 4];
    float4 o;
    o.x = a0.x * s + b.x; o.y = a0.y * s + b.y;
    o.z = a0.z * s + b.z; o.w = a0.w * s + b.w;
    if (do_relu) {
        o.x = fmaxf(o.x, 0.f); o.y = fmaxf(o.y, 0.f);
        o.z = fmaxf(o.z, 0.f); o.w = fmaxf(o.w, 0.f);
    }
    *(float4*)&out[(size_t)warp * DIM + lane * 4] = o;
}

// ---------------- column stats + z-score ----------------
__global__ void stats_kernel(const float* __restrict__ h_all) {
    int col = threadIdx.x;               // blockDim = 128
    int graph = blockIdx.y;
    const float* h = h_all + (size_t)graph * N_NODES * DIM;
    float sum = 0.f, sq = 0.f;
    for (int row = blockIdx.x; row < N_NODES; row += gridDim.x) {
        float v = h[(size_t)row * DIM + col];
        sum += v; sq += v * v;
    }
    atomicAdd(&g_sum  [graph * DIM + col], (double)sum);
    atomicAdd(&g_sumsq[graph * DIM + col], (double)sq);
}

__global__ void finalize_stats_kernel() {
    int c = threadIdx.x;
    if (c < 2 * DIM) {
        double mean = g_sum[c] / (double)N_NODES;
        double var  = (g_sumsq[c] - mean * mean * (double)N_NODES) / (double)(N_NODES - 1);
        g_mean[c] = (float)mean;
        g_istd[c] = (float)(1.0 / sqrt(var));
    }
}

__global__ void norm_kernel(float* __restrict__ h) {
    int i = blockIdx.x * blockDim.x + threadIdx.x;
    const int total = TWO_N * DIM / 4;
    if (i < total) {
        float4 v = ((float4*)h)[i];
        int c = (i * 4) & 127;
        int graph = (i >= N_NODES * DIM / 4) ? 1 : 0;
        int m = graph * DIM + c;
        v.x = (v.x - g_mean[m + 0]) * g_istd[m + 0];
        v.y = (v.y - g_mean[m + 1]) * g_istd[m + 1];
        v.z = (v.z - g_mean[m + 2]) * g_istd[m + 2];
        v.w = (v.w - g_mean[m + 3]) * g_istd[m + 3];
        ((float4*)h)[i] = v;
    }
}

// ---------------- launch ----------------
extern "C" void kernel_launch(void* const* d_in, const int* in_sizes, int n_in,
                              void* d_out, int out_size)
{
    const float* feat1 = (const float*)d_in[0];
    const float* feat2 = (const float*)d_in[1];
    const float* W1    = (const float*)d_in[2];
    const float* b1    = (const float*)d_in[3];
    const float* W2    = (const float*)d_in[4];
    const float* b2    = (const float*)d_in[5];
    const int*   src1  = (const int*)d_in[6];
    const int*   dst1  = (const int*)d_in[7];
    const int*   src2  = (const int*)d_in[8];
    const int*   dst2  = (const int*)d_in[9];
    float* out = (float*)d_out;

    // one-time setup (first call is the uncaptured correctness run)
    static cudaStream_t s2 = nullptr;
    static cudaEvent_t ev_fork = nullptr, ev_join = nullptr;
    if (!s2) {
        cudaStreamCreateWithFlags(&s2, cudaStreamNonBlocking);
        cudaEventCreateWithFlags(&ev_fork, cudaEventDisableTiming);
        cudaEventCreateWithFlags(&ev_join, cudaEventDisableTiming);
        cudaFuncSetAttribute(gemm_wmma_kernel,
                             cudaFuncAttributeMaxDynamicSharedMemorySize, GEMM_SMEM);
    }

    __half* p_xw = nullptr; float* p_h = nullptr;
    cudaGetSymbolAddress((void**)&p_xw, g_xw);
    cudaGetSymbolAddress((void**)&p_h,  g_h);

    const int NB_2N  = (TWO_N + 255) / 256;
    const int NB_2E  = (TWO_E + 255) / 256;
    const int NB_AGG = (TWO_N * 32 + 255) / 256;
    const int NB_NORM = (TWO_N * DIM / 4 + 255) / 256;

    // graph structure (both graphs at once)
    zero_kernel<<<NB_2N, 256>>>();
    degree_kernel<<<NB_2E, 256>>>(src1, dst1, src2, dst2);
    scan_partial_kernel<<<NCHUNK, 256>>>();   // also computes sout/sin

    // fork: CSR build tail overlaps with GEMM-1
    cudaEventRecord(ev_fork, 0);
    cudaStreamWaitEvent(s2, ev_fork, 0);
    scan_mid_kernel<<<1, 256, 0, s2>>>();
    scan_final_kernel<<<NCHUNK, 256, 0, s2>>>();
    scatter_kernel<<<NB_2E, 256, 0, s2>>>(src1, dst1, src2, dst2);
    cudaEventRecord(ev_join, s2);

    // layer 1 GEMM (needs only sout) runs concurrently with CSR tail
    gemm_wmma_kernel<<<148, 256, GEMM_SMEM>>>(feat1, feat2, W1, p_xw);
    cudaStreamWaitEvent(0, ev_join, 0);
    agg_kernel<<<NB_AGG, 256>>>(p_xw, b1, p_h, 1);

    // layer 2
    gemm_wmma_kernel<<<148, 256, GEMM_SMEM>>>(p_h, p_h + (size_t)N_NODES * DIM, W2, p_xw);
    agg_kernel<<<NB_AGG, 256>>>(p_xw, b2, out, 0);

    // z-score both halves
    stats_kernel<<<dim3(592, 2), 128>>>(out);
    finalize_stats_kernel<<<1, 256>>>();
    norm_kernel<<<NB_NORM, 256>>>(out);
}